// round 12
// baseline (speedup 1.0000x reference)
#include <cuda_runtime.h>
#include <cuda_bf16.h>

// Problem shape (fixed by the reference)
#define BB 16
#define TT 4096
#define HH 512
#define SS 64            // T-chunks per batch
#define TC (TT / SS)     // 64 rows per chunk
#define H4 (HH / 4)      // 128 float4 per row
#define GG 8             // sub-accumulator groups (chunk % GG)
#define NF4 (2 * HH / 4) // 256 float4 per (batch, group) accumulator

// Accumulators: [b][group][2*HH] floats (512 KB) + per-batch count + done flag.
// Zero-initialized at load; the finalizing CTA re-zeros -> graph-replayable.
__device__ float g_acc[BB][GG][2 * HH];
__device__ int   g_cnt[BB];
__device__ int   g_done[BB];

// Single kernel: CTA = (b, t-chunk). Streams its 64 rows (warp-coalesced
// 2 KiB rows, dead rows skipped), REDG-accumulates into its batch's
// sub-accumulator group, and the last CTA per batch finalizes.
__global__ __launch_bounds__(128) void pool_kernel(
    const float4* __restrict__ x,
    const int* __restrict__ lengths,
    const int* __restrict__ mask,        // jax bool materialized as int32
    float* __restrict__ out)
{
    const int blk = blockIdx.x;          // 0 .. B*SS-1
    const int b   = blk / SS;
    const int s   = blk % SS;
    const int tid = threadIdx.x;         // 0..127

    const int L  = lengths[b];
    const int t0 = s * TC;
    int Lc = L - t0;
    Lc = Lc < 0 ? 0 : (Lc > TC ? TC : Lc);

    const float4* __restrict__ xp = x + (size_t)b * TT * H4 + (size_t)t0 * H4 + tid;
    const int* __restrict__ mp = mask + (size_t)b * TT + t0;

    float4 ag = make_float4(0.f, 0.f, 0.f, 0.f);
    float4 al = make_float4(0.f, 0.f, 0.f, 0.f);
    int cnt = 0;

    // Region A: t < Lc — row always fetched (global view); mask gates local.
    int t = 0;
    #pragma unroll 8
    for (; t < Lc; ++t) {
        float4 v = xp[(size_t)t * H4];
        ag.x += v.x; ag.y += v.y; ag.z += v.z; ag.w += v.w;
        if (mp[t] != 0) { al.x += v.x; al.y += v.y; al.z += v.z; al.w += v.w; cnt++; }
    }
    // Region B: t >= Lc — fetch only masked rows (warp-uniform skip).
    #pragma unroll 4
    for (; t < TC; ++t) {
        if (mp[t] != 0) {
            float4 v = xp[(size_t)t * H4];
            al.x += v.x; al.y += v.y; al.z += v.z; al.w += v.w; cnt++;
        }
    }

    // Accumulate into this chunk's group (8 colliding CTAs per address).
    float* acc = &g_acc[b][s & (GG - 1)][0];
    const int h = 4 * tid;
    atomicAdd(&acc[h + 0], ag.x);
    atomicAdd(&acc[h + 1], ag.y);
    atomicAdd(&acc[h + 2], ag.z);
    atomicAdd(&acc[h + 3], ag.w);
    atomicAdd(&acc[HH + h + 0], al.x);
    atomicAdd(&acc[HH + h + 1], al.y);
    atomicAdd(&acc[HH + h + 2], al.z);
    atomicAdd(&acc[HH + h + 3], al.w);
    if (tid == 0 && cnt) atomicAdd(&g_cnt[b], cnt);

    // Last CTA of this batch finalizes.
    __shared__ int s_v;
    __threadfence();                     // order REDGs before the flag
    __syncthreads();
    if (tid == 0) s_v = atomicAdd(&g_done[b], 1);
    __syncthreads();
    if (s_v != SS - 1) return;

    __threadfence();                     // acquire all batch-mates' REDGs

    const int tot = g_cnt[b];
    const float dg = 1.0f / (float)(L   > 1 ? L   : 1);
    const float dl = 1.0f / (float)(tot > 1 ? tot : 1);

    // 256 float4 columns per batch; 2 per thread. Sum the 8 groups, divide,
    // write out, and re-zero the accumulators for the next replay.
    float4* o4 = reinterpret_cast<float4*>(out) + (size_t)b * NF4;
    #pragma unroll
    for (int k = 0; k < NF4 / 128; ++k) {        // k = 0, 1
        const int fc = k * 128 + tid;            // float4 column in [0, 256)
        float4 sum = make_float4(0.f, 0.f, 0.f, 0.f);
        #pragma unroll
        for (int g = 0; g < GG; ++g) {
            float4 v = reinterpret_cast<float4*>(&g_acc[b][g][0])[fc];
            sum.x += v.x; sum.y += v.y; sum.z += v.z; sum.w += v.w;
        }
        const float inv = (fc < H4) ? dg : dl;   // first 128 f4 = global half
        o4[fc] = make_float4(sum.x * inv, sum.y * inv, sum.z * inv, sum.w * inv);
        #pragma unroll
        for (int g = 0; g < GG; ++g)
            reinterpret_cast<float4*>(&g_acc[b][g][0])[fc] =
                make_float4(0.f, 0.f, 0.f, 0.f);
    }
    if (tid == 0) { g_cnt[b] = 0; g_done[b] = 0; }
}

extern "C" void kernel_launch(void* const* d_in, const int* in_sizes, int n_in,
                              void* d_out, int out_size)
{
    const float4* x       = (const float4*)d_in[0];   // [B,T,H] f32
    const int*    lengths = (const int*)d_in[1];      // [B] i32
    const int*    mask    = (const int*)d_in[2];      // [B,T] bool -> i32
    float*        out     = (float*)d_out;            // [B, 2H] f32

    pool_kernel<<<BB * SS, 128>>>(x, lengths, mask, out);
}